// round 10
// baseline (speedup 1.0000x reference)
#include <cuda_runtime.h>
#include <math.h>

// ---------------- packed f32x2 helpers (PTX-only; ptxas won't auto-fuse) ----
__device__ __forceinline__ unsigned long long fma2(unsigned long long a,
                                                   unsigned long long b,
                                                   unsigned long long c) {
    unsigned long long d;
    asm("fma.rn.f32x2 %0, %1, %2, %3;" : "=l"(d) : "l"(a), "l"(b), "l"(c));
    return d;
}
__device__ __forceinline__ unsigned long long pk2(float lo, float hi) {
    unsigned long long r;
    asm("mov.b64 %0, {%1, %2};" : "=l"(r) : "f"(lo), "f"(hi));
    return r;
}
union F4U { float4 f; struct { unsigned long long lo, hi; } u; };
union F2U { float2 f; unsigned long long u; };

// ---------------- per-row U features (fast intrinsics) ----------------------
__device__ __forceinline__ void compute_U(const float* __restrict__ p,
                                          float2* __restrict__ Urow) {
    const float LOG_TWO_PI = 1.8378770664093454836f;
    const float TWO_PI = 6.2831853071795864769f;
    const float EIGHT_PI = 25.132741228718345908f;
    const float EPS = 1e-6f;

    float eta = p[0], alpha = p[1], psi = p[2];
    float kappa = p[3], beta = p[4];
    float sa, ca, se, ce, sp, cp;
    __sincosf(alpha, &sa, &ca);
    __sincosf(eta,   &se, &ce);
    __sincosf(psi,   &sp, &cp);
    float g1[3] = { ca,       sa * ce,                  sa * se };
    float g2[3] = { -cp * sa, cp * ca * ce - sp * se,   cp * ca * se + sp * ce };
    float g3[3] = { sp * sa,  -sp * ca * ce - cp * se,  -sp * ca * se + cp * ce };

    float km = kappa - 2.f * beta, kp = kappa + 2.f * beta;
    float lkm = __logf(km), lkp = __logf(kp);

    float c  = LOG_TWO_PI + kappa - 0.5f * __logf(km * kp + EPS);
    float ck = __logf(-TWO_PI * (4.f * beta * beta + kappa - kappa * kappa)) + kappa
             - (1.5f * lkm + 1.5f * lkp + EPS);
    float k2 = kappa * kappa, b2 = beta * beta;
    float poly = k2 * k2 - 2.f * kappa * k2 + (2.f - 8.f * b2) * k2
               + 8.f * b2 * kappa + 16.f * b2 * b2 + 4.f * b2;
    float ckk = __logf(TWO_PI * poly) + kappa - (2.5f * lkm + 2.5f * lkp + EPS);
    float cbeta = __logf(EIGHT_PI * kappa) + __logf(beta)
                - (1.5f * lkm + 1.5f * lkp + EPS);

    float l1  = __expf(ck  - c);
    float ekk = __expf(ckk - c);
    float eb  = __expf(cbeta - c);
    float l2 = 0.5f * (1.f - ekk + eb);
    float l3 = 0.5f * (1.f - ekk - eb);

    float E00 = l1*g1[0]*g1[0] + l2*g2[0]*g2[0] + l3*g3[0]*g3[0];
    float E11 = l1*g1[1]*g1[1] + l2*g2[1]*g2[1] + l3*g3[1]*g3[1];
    float E22 = l1*g1[2]*g1[2] + l2*g2[2]*g2[2] + l3*g3[2]*g3[2];
    float E01 = l1*g1[0]*g1[1] + l2*g2[0]*g2[1] + l3*g3[0]*g3[1];
    float E02 = l1*g1[0]*g1[2] + l2*g2[0]*g2[2] + l3*g3[0]*g3[2];
    float E12 = l1*g1[1]*g1[2] + l2*g2[1]*g2[2] + l3*g3[1]*g3[2];

    float Ex0 = l1 * g1[0], Ex1 = l1 * g1[1], Ex2 = l1 * g1[2];

    float qa2 = E00*g2[0]*g2[0] + E11*g2[1]*g2[1] + E22*g2[2]*g2[2]
              + 2.f*(E01*g2[0]*g2[1] + E02*g2[0]*g2[2] + E12*g2[1]*g2[2]);
    float qa3 = E00*g3[0]*g3[0] + E11*g3[1]*g3[1] + E22*g3[2]*g3[2]
              + 2.f*(E01*g3[0]*g3[1] + E02*g3[0]*g3[2] + E12*g3[1]*g3[2]);

    float kdot = kappa * (g1[0]*Ex0 + g1[1]*Ex1 + g1[2]*Ex2);
    float S = -c + kdot + beta * (qa2 - qa3);

    float u[11] = { S, 1.f, Ex0, Ex1, Ex2, E00, E11, E22,
                    2.f*E01, 2.f*E02, 2.f*E12 };
#pragma unroll
    for (int k = 0; k < 11; k++) Urow[k] = make_float2(u[k], u[k]);
    Urow[11] = make_float2(0.f, 0.f);
}

// ---------------- per-col V features (10 components; v0=1 folded out) -------
__device__ __forceinline__ void compute_V(float eta, float alpha, float psi,
                                          float kappa, float beta,
                                          float v[10]) {
    const float LOG_TWO_PI = 1.8378770664093454836f;
    const float EPS = 1e-6f;
    float sa, ca, se, ce, sp, cp;
    __sincosf(alpha, &sa, &ca);
    __sincosf(eta,   &se, &ce);
    __sincosf(psi,   &sp, &cp);
    float g1x = ca,       g1y = sa * ce,                 g1z = sa * se;
    float g2x = -cp * sa, g2y = cp * ca * ce - sp * se,  g2z = cp * ca * se + sp * ce;
    float g3x = sp * sa,  g3y = -sp * ca * ce - cp * se, g3z = -sp * ca * se + cp * ce;

    float km = kappa - 2.f * beta, kp = kappa + 2.f * beta;
    v[0] = LOG_TWO_PI + kappa - 0.5f * __logf(km * kp + EPS);   // c_b
    v[1] = -kappa * g1x;
    v[2] = -kappa * g1y;
    v[3] = -kappa * g1z;
    v[4] = beta * (g3x*g3x - g2x*g2x);
    v[5] = beta * (g3y*g3y - g2y*g2y);
    v[6] = beta * (g3z*g3z - g2z*g2z);
    v[7] = beta * (g3x*g3y - g2x*g2y);
    v[8] = beta * (g3x*g3z - g2x*g2z);
    v[9] = beta * (g3y*g3z - g2y*g2z);
}

// ---------------- fused kernel ----------------------------------------------
// 128 threads; tile = 8 rows x 256 cols; 2 cols/thread.
// grid = (M/256) x (N/8) = 2048 blocks -> 8192 warps chip-wide (2x chip),
// <=51 regs (launch_bounds 10) -> ~40 resident warps/SM.
#define KLD_THREADS 128
#define KLD_ROWS    8

__global__ void __launch_bounds__(KLD_THREADS, 10)
kld_fused(const float* __restrict__ pred, const float* __restrict__ targ,
          float* __restrict__ out, int N, int M) {
    int tid  = threadIdx.x;
    int col  = (blockIdx.x * KLD_THREADS + tid) * 2;
    int row0 = blockIdx.y * KLD_ROWS;
    int nrows = N - row0;
    if (nrows > KLD_ROWS) nrows = KLD_ROWS;

    __shared__ float2 sU[KLD_ROWS][12];

    // --- U: threads 0..nrows-1, one row each --------------------------------
    if (tid < nrows)
        compute_U(pred + (size_t)(row0 + tid) * 5, sU[tid]);

    // --- V: each thread, 2 cols (10 floats, 40B-aligned: 5x LDG.64) ---------
    bool vec = ((M & 1) == 0) && (col + 2 <= M);
    unsigned long long vA[10];

    if (vec) {
        float tp[10];
        const float2* src = reinterpret_cast<const float2*>(targ + (size_t)col * 5);
#pragma unroll
        for (int q = 0; q < 5; q++)
            *reinterpret_cast<float2*>(&tp[q * 2]) = src[q];

        float v0[10], v1[10];
        compute_V(tp[0], tp[1], tp[2], tp[3], tp[4], v0);
        compute_V(tp[5], tp[6], tp[7], tp[8], tp[9], v1);
#pragma unroll
        for (int k = 0; k < 10; k++) vA[k] = pk2(v0[k], v1[k]);
    }

    __syncthreads();

    if (vec) {
        if (nrows == KLD_ROWS) {
#pragma unroll
            for (int r = 0; r < KLD_ROWS; r++) {
                const float4* uj = reinterpret_cast<const float4*>(sU[r]);
                F4U u0; u0.f = uj[0];                    // {S,S,1,1}
                unsigned long long acc = fma2(u0.u.hi, vA[0], u0.u.lo);  // S + c_b
#pragma unroll
                for (int j = 1; j < 5; j++) {
                    F4U u; u.f = uj[j];                  // dup pairs
                    acc = fma2(u.u.lo, vA[2*j-1], acc);
                    acc = fma2(u.u.hi, vA[2*j],   acc);
                }
                F4U u5; u5.f = uj[5];                    // {u10,u10,0,0}
                acc = fma2(u5.u.lo, vA[9], acc);
                F2U res; res.u = acc;
                *reinterpret_cast<float2*>(out + (size_t)(row0 + r) * M + col) = res.f;
            }
        } else {
            for (int r = 0; r < nrows; r++) {
                const float4* uj = reinterpret_cast<const float4*>(sU[r]);
                F4U u0; u0.f = uj[0];
                unsigned long long acc = fma2(u0.u.hi, vA[0], u0.u.lo);
#pragma unroll
                for (int j = 1; j < 5; j++) {
                    F4U u; u.f = uj[j];
                    acc = fma2(u.u.lo, vA[2*j-1], acc);
                    acc = fma2(u.u.hi, vA[2*j],   acc);
                }
                F4U u5; u5.f = uj[5];
                acc = fma2(u5.u.lo, vA[9], acc);
                F2U res; res.u = acc;
                *reinterpret_cast<float2*>(out + (size_t)(row0 + r) * M + col) = res.f;
            }
        }
    } else if (col < M) {
        // scalar tail path
        float vs[10];
        int ncols = M - col; if (ncols > 2) ncols = 2;
        for (int cc = 0; cc < ncols; cc++) {
            const float* p = targ + (size_t)(col + cc) * 5;
            compute_V(p[0], p[1], p[2], p[3], p[4], vs);
            for (int r = 0; r < nrows; r++) {
                float acc = sU[r][0].x + vs[0];          // S + c_b
#pragma unroll
                for (int k = 0; k < 9; k++)
                    acc = fmaf(sU[r][k + 2].x, vs[k + 1], acc);
                out[(size_t)(row0 + r) * M + col + cc] = acc;
            }
        }
    }
}

extern "C" void kernel_launch(void* const* d_in, const int* in_sizes, int n_in,
                              void* d_out, int out_size) {
    const float* pred = (const float*)d_in[0];
    const float* targ = (const float*)d_in[1];
    float* out = (float*)d_out;
    int N = in_sizes[0] / 5;
    int M = in_sizes[1] / 5;

    dim3 grid((M + KLD_THREADS * 2 - 1) / (KLD_THREADS * 2),
              (N + KLD_ROWS - 1) / KLD_ROWS);
    kld_fused<<<grid, KLD_THREADS>>>(pred, targ, out, N, M);
}

// round 11
// speedup vs baseline: 1.2657x; 1.2657x over previous
#include <cuda_runtime.h>
#include <math.h>

typedef unsigned long long ull;

// ---------------- packed f32x2 helpers (PTX-only; ptxas won't auto-fuse) ----
__device__ __forceinline__ ull fma2(ull a, ull b, ull c) {
    ull d; asm("fma.rn.f32x2 %0, %1, %2, %3;" : "=l"(d) : "l"(a), "l"(b), "l"(c));
    return d;
}
__device__ __forceinline__ ull mul2(ull a, ull b) {
    ull d; asm("mul.rn.f32x2 %0, %1, %2;" : "=l"(d) : "l"(a), "l"(b));
    return d;
}
__device__ __forceinline__ ull add2(ull a, ull b) {
    ull d; asm("add.rn.f32x2 %0, %1, %2;" : "=l"(d) : "l"(a), "l"(b));
    return d;
}
__device__ __forceinline__ ull sub2(ull a, ull b) {
    ull d; asm("sub.rn.f32x2 %0, %1, %2;" : "=l"(d) : "l"(a), "l"(b));
    return d;
}
__device__ __forceinline__ ull pk2(float lo, float hi) {
    ull r; asm("mov.b64 %0, {%1, %2};" : "=l"(r) : "f"(lo), "f"(hi));
    return r;
}
__device__ __forceinline__ void upk2(ull a, float& lo, float& hi) {
    asm("mov.b64 {%0, %1}, %2;" : "=f"(lo), "=f"(hi) : "l"(a));
}
union F4U { float4 f; struct { ull lo, hi; } u; };

// ---------------- per-row U features (fast intrinsics) ----------------------
__device__ __forceinline__ void compute_U(const float* __restrict__ p,
                                          float2* __restrict__ Urow) {
    const float LOG_TWO_PI = 1.8378770664093454836f;
    const float TWO_PI = 6.2831853071795864769f;
    const float EIGHT_PI = 25.132741228718345908f;
    const float EPS = 1e-6f;

    float eta = p[0], alpha = p[1], psi = p[2];
    float kappa = p[3], beta = p[4];
    float sa, ca, se, ce, sp, cp;
    __sincosf(alpha, &sa, &ca);
    __sincosf(eta,   &se, &ce);
    __sincosf(psi,   &sp, &cp);
    float g1[3] = { ca,       sa * ce,                  sa * se };
    float g2[3] = { -cp * sa, cp * ca * ce - sp * se,   cp * ca * se + sp * ce };
    float g3[3] = { sp * sa,  -sp * ca * ce - cp * se,  -sp * ca * se + cp * ce };

    float km = kappa - 2.f * beta, kp = kappa + 2.f * beta;
    float lkm = __logf(km), lkp = __logf(kp);

    float c  = LOG_TWO_PI + kappa - 0.5f * __logf(km * kp + EPS);
    float ck = __logf(-TWO_PI * (4.f * beta * beta + kappa - kappa * kappa)) + kappa
             - (1.5f * lkm + 1.5f * lkp + EPS);
    float k2 = kappa * kappa, b2 = beta * beta;
    float poly = k2 * k2 - 2.f * kappa * k2 + (2.f - 8.f * b2) * k2
               + 8.f * b2 * kappa + 16.f * b2 * b2 + 4.f * b2;
    float ckk = __logf(TWO_PI * poly) + kappa - (2.5f * lkm + 2.5f * lkp + EPS);
    float cbeta = __logf(EIGHT_PI * kappa) + __logf(beta)
                - (1.5f * lkm + 1.5f * lkp + EPS);

    float l1  = __expf(ck  - c);
    float ekk = __expf(ckk - c);
    float eb  = __expf(cbeta - c);
    float l2 = 0.5f * (1.f - ekk + eb);
    float l3 = 0.5f * (1.f - ekk - eb);

    float E00 = l1*g1[0]*g1[0] + l2*g2[0]*g2[0] + l3*g3[0]*g3[0];
    float E11 = l1*g1[1]*g1[1] + l2*g2[1]*g2[1] + l3*g3[1]*g3[1];
    float E22 = l1*g1[2]*g1[2] + l2*g2[2]*g2[2] + l3*g3[2]*g3[2];
    float E01 = l1*g1[0]*g1[1] + l2*g2[0]*g2[1] + l3*g3[0]*g3[1];
    float E02 = l1*g1[0]*g1[2] + l2*g2[0]*g2[2] + l3*g3[0]*g3[2];
    float E12 = l1*g1[1]*g1[2] + l2*g2[1]*g2[2] + l3*g3[1]*g3[2];

    float Ex0 = l1 * g1[0], Ex1 = l1 * g1[1], Ex2 = l1 * g1[2];

    float qa2 = E00*g2[0]*g2[0] + E11*g2[1]*g2[1] + E22*g2[2]*g2[2]
              + 2.f*(E01*g2[0]*g2[1] + E02*g2[0]*g2[2] + E12*g2[1]*g2[2]);
    float qa3 = E00*g3[0]*g3[0] + E11*g3[1]*g3[1] + E22*g3[2]*g3[2]
              + 2.f*(E01*g3[0]*g3[1] + E02*g3[0]*g3[2] + E12*g3[1]*g3[2]);

    float kdot = kappa * (g1[0]*Ex0 + g1[1]*Ex1 + g1[2]*Ex2);
    float S = -c + kdot + beta * (qa2 - qa3);

    float u[11] = { S, 1.f, Ex0, Ex1, Ex2, E00, E11, E22,
                    2.f*E01, 2.f*E02, 2.f*E12 };
#pragma unroll
    for (int k = 0; k < 11; k++) Urow[k] = make_float2(u[k], u[k]);
    Urow[11] = make_float2(0.f, 0.f);
}

// ---------------- packed 2-column V (f32x2 datapath) -------------------------
// ta/tb: 5 raw params for the two columns. v[0..9] packed {colA,colB}.
__device__ __forceinline__ void compute_V2(const float* __restrict__ ta,
                                           const float* __restrict__ tb,
                                           ull v[10]) {
    const float LOG_TWO_PI = 1.8378770664093454836f;
    // scalar MUFU work per column
    float sa0, ca0, se0, ce0, sp0, cp0;
    float sa1, ca1, se1, ce1, sp1, cp1;
    __sincosf(ta[1], &sa0, &ca0);  __sincosf(tb[1], &sa1, &ca1);
    __sincosf(ta[0], &se0, &ce0);  __sincosf(tb[0], &se1, &ce1);
    __sincosf(ta[2], &sp0, &cp0);  __sincosf(tb[2], &sp1, &cp1);

    ull sa = pk2(sa0, sa1), ca = pk2(ca0, ca1);
    ull se = pk2(se0, se1), ce = pk2(ce0, ce1);
    ull sp = pk2(sp0, sp1), cp = pk2(cp0, cp1);
    ull kap = pk2(ta[3], tb[3]), bet = pk2(ta[4], tb[4]);
    const ull ZERO = 0ull;                      // {+0,+0}

    // frame vectors, packed
    ull g1y  = mul2(sa, ce);
    ull g1z  = mul2(sa, se);
    ull cpca = mul2(cp, ca);
    ull spca = mul2(sp, ca);
    ull g2x  = sub2(ZERO, mul2(cp, sa));
    ull g2y  = sub2(mul2(cpca, ce), mul2(sp, se));
    ull g2z  = fma2(cpca, se, mul2(sp, ce));
    ull g3x  = mul2(sp, sa);
    ull g3y  = sub2(ZERO, fma2(spca, ce, mul2(cp, se)));
    ull g3z  = sub2(mul2(cp, ce), mul2(spca, se));

    // v0 = c_b (needs scalar logs)
    ull bb = add2(bet, bet);
    ull km = sub2(kap, bb);
    ull kp = add2(kap, bb);
    ull pr = fma2(km, kp, pk2(1e-6f, 1e-6f));
    float pr0, pr1; upk2(pr, pr0, pr1);
    float cb0 = LOG_TWO_PI + ta[3] - 0.5f * __logf(pr0);
    float cb1 = LOG_TWO_PI + tb[3] - 0.5f * __logf(pr1);
    v[0] = pk2(cb0, cb1);

    // v1..v3 = -kappa * g1
    ull nk = sub2(ZERO, kap);
    v[1] = mul2(nk, ca);
    v[2] = mul2(nk, g1y);
    v[3] = mul2(nk, g1z);

    // v4..v9 = beta * (g3 g3^T - g2 g2^T)
    ull bg2x = mul2(bet, g2x), bg2y = mul2(bet, g2y), bg2z = mul2(bet, g2z);
    ull bg3x = mul2(bet, g3x), bg3y = mul2(bet, g3y), bg3z = mul2(bet, g3z);
    v[4] = sub2(mul2(bg3x, g3x), mul2(bg2x, g2x));
    v[5] = sub2(mul2(bg3y, g3y), mul2(bg2y, g2y));
    v[6] = sub2(mul2(bg3z, g3z), mul2(bg2z, g2z));
    v[7] = sub2(mul2(bg3x, g3y), mul2(bg2x, g2y));
    v[8] = sub2(mul2(bg3x, g3z), mul2(bg2x, g2z));
    v[9] = sub2(mul2(bg3y, g3z), mul2(bg2y, g2z));
}

// scalar V for the tail path
__device__ __forceinline__ void compute_V(float eta, float alpha, float psi,
                                          float kappa, float beta,
                                          float v[10]) {
    const float LOG_TWO_PI = 1.8378770664093454836f;
    const float EPS = 1e-6f;
    float sa, ca, se, ce, sp, cp;
    __sincosf(alpha, &sa, &ca);
    __sincosf(eta,   &se, &ce);
    __sincosf(psi,   &sp, &cp);
    float g1x = ca,       g1y = sa * ce,                 g1z = sa * se;
    float g2x = -cp * sa, g2y = cp * ca * ce - sp * se,  g2z = cp * ca * se + sp * ce;
    float g3x = sp * sa,  g3y = -sp * ca * ce - cp * se, g3z = -sp * ca * se + cp * ce;
    float km = kappa - 2.f * beta, kp = kappa + 2.f * beta;
    v[0] = LOG_TWO_PI + kappa - 0.5f * __logf(km * kp + EPS);
    v[1] = -kappa * g1x;  v[2] = -kappa * g1y;  v[3] = -kappa * g1z;
    v[4] = beta * (g3x*g3x - g2x*g2x);
    v[5] = beta * (g3y*g3y - g2y*g2y);
    v[6] = beta * (g3z*g3z - g2z*g2z);
    v[7] = beta * (g3x*g3y - g2x*g2y);
    v[8] = beta * (g3x*g3z - g2x*g2z);
    v[9] = beta * (g3y*g3z - g2y*g2z);
}

// ---------------- fused kernel (R4 shape) ------------------------------------
// 128 threads; tile = 8 rows x 512 cols; 4 cols/thread; 1024 blocks.
#define KLD_THREADS 128
#define KLD_ROWS    8

__global__ void __launch_bounds__(KLD_THREADS, 8)
kld_fused(const float* __restrict__ pred, const float* __restrict__ targ,
          float* __restrict__ out, int N, int M) {
    int tid  = threadIdx.x;
    int col  = (blockIdx.x * KLD_THREADS + tid) * 4;
    int row0 = blockIdx.y * KLD_ROWS;
    int nrows = N - row0;
    if (nrows > KLD_ROWS) nrows = KLD_ROWS;

    __shared__ float2 sU[KLD_ROWS][12];

    // --- U: threads 0..nrows-1, one row each --------------------------------
    if (tid < nrows)
        compute_U(pred + (size_t)(row0 + tid) * 5, sU[tid]);

    // --- V: 4 cols as two packed pairs --------------------------------------
    bool vec = ((M & 3) == 0) && (col + 4 <= M);
    ull vA[10], vB[10];

    if (vec) {
        float tp[20];
        const float4* src = reinterpret_cast<const float4*>(targ + (size_t)col * 5);
#pragma unroll
        for (int q = 0; q < 5; q++)
            *reinterpret_cast<float4*>(&tp[q * 4]) = src[q];

        compute_V2(tp,      tp + 5,  vA);
        compute_V2(tp + 10, tp + 15, vB);
    }

    __syncthreads();

    if (vec) {
        if (nrows == KLD_ROWS) {
#pragma unroll
            for (int r = 0; r < KLD_ROWS; r++) {
                const float4* uj = reinterpret_cast<const float4*>(sU[r]);
                F4U u0; u0.f = uj[0];                    // {S,S,1,1}
                ull alo = fma2(u0.u.hi, vA[0], u0.u.lo); // S + c_b
                ull ahi = fma2(u0.u.hi, vB[0], u0.u.lo);
#pragma unroll
                for (int j = 1; j < 5; j++) {
                    F4U u; u.f = uj[j];                  // dup pairs
                    alo = fma2(u.u.lo, vA[2*j-1], alo); ahi = fma2(u.u.lo, vB[2*j-1], ahi);
                    alo = fma2(u.u.hi, vA[2*j],   alo); ahi = fma2(u.u.hi, vB[2*j],   ahi);
                }
                F4U u5; u5.f = uj[5];                    // {u10,u10,0,0}
                alo = fma2(u5.u.lo, vA[9], alo); ahi = fma2(u5.u.lo, vB[9], ahi);
                F4U res; res.u.lo = alo; res.u.hi = ahi;
                *reinterpret_cast<float4*>(out + (size_t)(row0 + r) * M + col) = res.f;
            }
        } else {
            for (int r = 0; r < nrows; r++) {
                const float4* uj = reinterpret_cast<const float4*>(sU[r]);
                F4U u0; u0.f = uj[0];
                ull alo = fma2(u0.u.hi, vA[0], u0.u.lo);
                ull ahi = fma2(u0.u.hi, vB[0], u0.u.lo);
#pragma unroll
                for (int j = 1; j < 5; j++) {
                    F4U u; u.f = uj[j];
                    alo = fma2(u.u.lo, vA[2*j-1], alo); ahi = fma2(u.u.lo, vB[2*j-1], ahi);
                    alo = fma2(u.u.hi, vA[2*j],   alo); ahi = fma2(u.u.hi, vB[2*j],   ahi);
                }
                F4U u5; u5.f = uj[5];
                alo = fma2(u5.u.lo, vA[9], alo); ahi = fma2(u5.u.lo, vB[9], ahi);
                F4U res; res.u.lo = alo; res.u.hi = ahi;
                *reinterpret_cast<float4*>(out + (size_t)(row0 + r) * M + col) = res.f;
            }
        }
    } else if (col < M) {
        // scalar tail path
        float vs[10];
        int ncols = M - col; if (ncols > 4) ncols = 4;
        for (int cc = 0; cc < ncols; cc++) {
            const float* p = targ + (size_t)(col + cc) * 5;
            compute_V(p[0], p[1], p[2], p[3], p[4], vs);
            for (int r = 0; r < nrows; r++) {
                float acc = sU[r][0].x + vs[0];          // S + c_b
#pragma unroll
                for (int k = 0; k < 9; k++)
                    acc = fmaf(sU[r][k + 2].x, vs[k + 1], acc);
                out[(size_t)(row0 + r) * M + col + cc] = acc;
            }
        }
    }
}

extern "C" void kernel_launch(void* const* d_in, const int* in_sizes, int n_in,
                              void* d_out, int out_size) {
    const float* pred = (const float*)d_in[0];
    const float* targ = (const float*)d_in[1];
    float* out = (float*)d_out;
    int N = in_sizes[0] / 5;
    int M = in_sizes[1] / 5;

    dim3 grid((M + KLD_THREADS * 4 - 1) / (KLD_THREADS * 4),
              (N + KLD_ROWS - 1) / KLD_ROWS);
    kld_fused<<<grid, KLD_THREADS>>>(pred, targ, out, N, M);
}